// round 9
// baseline (speedup 1.0000x reference)
#include <cuda_runtime.h>

#define BB   1024
#define CC   3
#define PROW 4
#define PCOL 5
#define PP   20      // PROW*PCOL
#define HID  32
#define HH   224
#define WW   220
#define PH   56      // HH/PROW
#define PW   44      // WW/PCOL
#define W4   55      // WW/4 float4 per row
#define PW4  11      // PW/4 float4 per column-patch

#define IPB  4                 // images per block in the MLP kernel
#define MLPT (IPB * PP)        // 80 threads
#define NMLPB (BB / IPB)       // 256 blocks -> every SM gets work

// per-(image, patch, channel) partial sums
__device__ float g_scratch[BB * PP * CC];

// ---------------------------------------------------------------------------
// Kernel 1: pooling — unchanged from the proven 6.82 TB/s config.
// grid = (BB, CC); block = (56, 8). No fences, no atomics.
// ---------------------------------------------------------------------------
__global__ __launch_bounds__(448)
void nam_pool_kernel(const float* __restrict__ x)
{
    const int b  = blockIdx.x;
    const int c  = blockIdx.y;
    const int tx = threadIdx.x;   // 0..55 (55 idle for loads)
    const int ty = threadIdx.y;   // 0..7

    const float4* base = (const float4*)(x) + (size_t)(b * CC + c) * (HH * W4);

    float acc[PROW] = {0.f, 0.f, 0.f, 0.f};

    if (tx < W4) {
        #pragma unroll
        for (int pr = 0; pr < PROW; pr++) {
            #pragma unroll
            for (int i = 0; i < PH / 8; i++) {          // 7 row-groups
                const int h = pr * PH + i * 8 + ty;
                float4 v = base[h * W4 + tx];
                acc[pr] += (v.x + v.y) + (v.z + v.w);
            }
        }
    }

    __shared__ float part[PROW][8][56];
    #pragma unroll
    for (int pr = 0; pr < PROW; pr++)
        part[pr][ty][tx] = acc[pr];                      // tx==55 stores 0
    __syncthreads();

    const int tid = ty * 56 + tx;
    if (tid < PP) {
        const int pr = tid / PCOL;
        const int pc = tid % PCOL;
        float s = 0.f;
        #pragma unroll
        for (int yy = 0; yy < 8; yy++) {
            float a = 0.f;
            #pragma unroll
            for (int k = 0; k < PW4; k++)
                a += part[pr][yy][pc * PW4 + k];
            s += a;
        }
        g_scratch[(b * PP + tid) * CC + c] = s;
    }
}

// ---------------------------------------------------------------------------
// Kernel 2: MLP, one thread per (image, patch). grid = 256 blocks (all SMs
// covered), block = 80 threads. Weights staged into padded shared
// ([PP][HID+1] -> conflict-free). Score reduced via shared.
// ---------------------------------------------------------------------------
__global__ __launch_bounds__(MLPT)
void nam_mlp_kernel(const float* __restrict__ w1,
                    const float* __restrict__ b1,
                    const float* __restrict__ w2,
                    const float* __restrict__ b2,
                    float* __restrict__ out)
{
    __shared__ float sw1[PP][HID + 1];
    __shared__ float sb1[PP][HID + 1];
    __shared__ float sw2[PP][HID + 1];
    __shared__ float sb2[PP];
    __shared__ float scon[IPB][PP];

    const int t = threadIdx.x;

    // cooperative weight staging: PP*HID = 640 elems per array
    for (int idx = t; idx < PP * HID; idx += MLPT) {
        const int p = idx / HID, k = idx % HID;
        sw1[p][k] = w1[idx];
        sb1[p][k] = b1[idx];
        sw2[p][k] = w2[idx];
    }
    if (t < PP) sb2[t] = b2[t];
    __syncthreads();

    const int i = t / PP;                 // local image 0..3
    const int p = t % PP;                 // patch 0..19
    const int b = blockIdx.x * IPB + i;

    const float* sp = &g_scratch[(b * PP + p) * CC];
    const float f = (sp[0] + sp[1] + sp[2]) * (1.0f / (CC * PH * PW));

    float o = sb2[p];
    #pragma unroll
    for (int k = 0; k < HID; k++) {
        float h = fmaf(f, sw1[p][k], sb1[p][k]);
        h = fmaxf(h, 0.0f);
        o = fmaf(h, sw2[p][k], o);
    }
    out[BB + b * PP + p] = o;             // contribs section
    scon[i][p] = o;
    __syncthreads();

    if (t < IPB) {
        float sc = 0.f;
        #pragma unroll
        for (int q = 0; q < PP; q++)
            sc += scon[t][q];
        out[blockIdx.x * IPB + t] = sc;   // score section
    }
}

extern "C" void kernel_launch(void* const* d_in, const int* in_sizes, int n_in,
                              void* d_out, int out_size)
{
    const float* x  = (const float*)d_in[0];
    const float* w1 = (const float*)d_in[1];
    const float* b1 = (const float*)d_in[2];
    const float* w2 = (const float*)d_in[3];
    const float* b2 = (const float*)d_in[4];
    float* out = (float*)d_out;

    nam_pool_kernel<<<dim3(BB, CC), dim3(56, 8)>>>(x);
    nam_mlp_kernel<<<NMLPB, MLPT>>>(w1, b1, w2, b2, out);
}

// round 12
// speedup vs baseline: 1.0413x; 1.0413x over previous
#include <cuda_runtime.h>

#define BB   1024
#define CC   3
#define PROW 4
#define PCOL 5
#define PP   20      // PROW*PCOL
#define HID  32
#define HH   224
#define WW   220
#define PH   56      // HH/PROW
#define PW   44      // PW = WW/PCOL
#define W4   55      // WW/4 float4 per row
#define PW4  11      // PW/4 float4 per column-patch

#define KG   4                    // k-groups per (image,patch)
#define KS   (HID / KG)           // 8 k's per group
#define IPB  4                    // images per MLP block
#define MLPT (IPB * PP * KG)      // 320 threads
#define NMLPB (BB / IPB)          // 256 blocks

// per-(image, patch, channel) partial sums
__device__ float g_scratch[BB * PP * CC];

// ---------------------------------------------------------------------------
// Kernel 1: pooling — unchanged (measured 6.83 TB/s; at the HBM wall).
// grid = (BB, CC); block = (56, 8). No fences, no atomics.
// ---------------------------------------------------------------------------
__global__ __launch_bounds__(448)
void nam_pool_kernel(const float* __restrict__ x)
{
    const int b  = blockIdx.x;
    const int c  = blockIdx.y;
    const int tx = threadIdx.x;   // 0..55 (55 idle for loads)
    const int ty = threadIdx.y;   // 0..7

    const float4* base = (const float4*)(x) + (size_t)(b * CC + c) * (HH * W4);

    float acc[PROW] = {0.f, 0.f, 0.f, 0.f};

    if (tx < W4) {
        #pragma unroll
        for (int pr = 0; pr < PROW; pr++) {
            #pragma unroll
            for (int i = 0; i < PH / 8; i++) {          // 7 row-groups
                const int h = pr * PH + i * 8 + ty;
                float4 v = base[h * W4 + tx];
                acc[pr] += (v.x + v.y) + (v.z + v.w);
            }
        }
    }

    __shared__ float part[PROW][8][56];
    #pragma unroll
    for (int pr = 0; pr < PROW; pr++)
        part[pr][ty][tx] = acc[pr];                      // tx==55 stores 0
    __syncthreads();

    const int tid = ty * 56 + tx;
    if (tid < PP) {
        const int pr = tid / PCOL;
        const int pc = tid % PCOL;
        float s = 0.f;
        #pragma unroll
        for (int yy = 0; yy < 8; yy++) {
            float a = 0.f;
            #pragma unroll
            for (int k = 0; k < PW4; k++)
                a += part[pr][yy][pc * PW4 + k];
            s += a;
        }
        g_scratch[(b * PP + tid) * CC + c] = s;
    }
}

// ---------------------------------------------------------------------------
// Kernel 2: MLP with k-parallelism. Thread t = ((i*PP + p)*KG + kg):
//   - consecutive t -> consecutive 32B of w1/b1/w2 (fully coalesced LDG,
//     no shared staging, no first __syncthreads)
//   - serial chain is only KS=8 accum FMAs + 2 shfl steps.
// grid = 256, block = 320.
// ---------------------------------------------------------------------------
__global__ __launch_bounds__(MLPT)
void nam_mlp_kernel(const float* __restrict__ w1,
                    const float* __restrict__ b1,
                    const float* __restrict__ w2,
                    const float* __restrict__ b2,
                    float* __restrict__ out)
{
    __shared__ float scon[IPB][PP];

    const int t  = threadIdx.x;
    const int kg = t & (KG - 1);          // 0..3
    const int ip = t >> 2;                // (i*PP + p), 0..79
    const int p  = ip % PP;
    const int i  = ip / PP;
    const int b  = blockIdx.x * IPB + i;

    // feature for (b, p): all 4 kg-lanes read the same 3 floats (broadcast)
    const float* sp = &g_scratch[(b * PP + p) * CC];
    const float f = (sp[0] + sp[1] + sp[2]) * (1.0f / (CC * PH * PW));

    // this lane's 8-wide k slice, coalesced float4 x2 per array
    const int base = p * HID + kg * KS;
    const float4* w1v = (const float4*)(w1 + base);
    const float4* b1v = (const float4*)(b1 + base);
    const float4* w2v = (const float4*)(w2 + base);

    float o = 0.f;
    #pragma unroll
    for (int q = 0; q < KS / 4; q++) {    // 2 float4 groups
        float4 a = w1v[q], c = b1v[q], w = w2v[q];
        o = fmaf(fmaxf(fmaf(f, a.x, c.x), 0.f), w.x, o);
        o = fmaf(fmaxf(fmaf(f, a.y, c.y), 0.f), w.y, o);
        o = fmaf(fmaxf(fmaf(f, a.z, c.z), 0.f), w.z, o);
        o = fmaf(fmaxf(fmaf(f, a.w, c.w), 0.f), w.w, o);
    }

    // reduce the 4 kg-lanes (aligned 4-lane groups within a warp)
    o += __shfl_down_sync(0xFFFFFFFFu, o, 2);
    o += __shfl_down_sync(0xFFFFFFFFu, o, 1);

    if (kg == 0) {
        o += b2[p];
        out[BB + b * PP + p] = o;         // contribs section
        scon[i][p] = o;
    }
    __syncthreads();

    if (t < IPB) {
        float sc = 0.f;
        #pragma unroll
        for (int q = 0; q < PP; q++)
            sc += scon[t][q];
        out[blockIdx.x * IPB + t] = sc;   // score section
    }
}

extern "C" void kernel_launch(void* const* d_in, const int* in_sizes, int n_in,
                              void* d_out, int out_size)
{
    const float* x  = (const float*)d_in[0];
    const float* w1 = (const float*)d_in[1];
    const float* b1 = (const float*)d_in[2];
    const float* w2 = (const float*)d_in[3];
    const float* b2 = (const float*)d_in[4];
    float* out = (float*)d_out;

    nam_pool_kernel<<<dim3(BB, CC), dim3(56, 8)>>>(x);
    nam_mlp_kernel<<<NMLPB, MLPT>>>(w1, b1, w2, b2, out);
}